// round 10
// baseline (speedup 1.0000x reference)
#include <cuda_runtime.h>
#include <cuda_bf16.h>
#include <stdint.h>
#include <math.h>

#define Bb 512
#define Nn 16
#define Cc 256
#define Kk 8192
#define MAXC 512

// ---------------- device globals (no allocations allowed) ----------------
__device__ float g_frest[Bb*Nn*Cc];
__device__ float g_fhat [Bb*Nn*Cc];
__device__ float g_rest [Bb*Nn*Cc];
__device__ __nv_bfloat16 g_rest_h[Bb*Nn*Cc];
__device__ __nv_bfloat16 g_emb_h[Kk*Cc];
__device__ float g_rsq  [Bb*Nn];
__device__ float g_esq  [Kk];
__device__ unsigned int g_dmin[Bb*Nn];          // fkey32 of min d-tilde
__device__ int g_ccnt[Bb*Nn];
__device__ int g_cand[Bb*Nn*MAXC];
__device__ unsigned long long g_win[Bb*Nn];
__device__ double g_loss;

// ---------------- helpers ----------------
__device__ __forceinline__ unsigned int smem_u32(const void* p){
    unsigned int a;
    asm("{ .reg .u64 t; cvta.to.shared.u64 t, %1; cvt.u32.u64 %0, t; }" : "=r"(a) : "l"(p));
    return a;
}
#define CP_ASYNC16(dst,src) asm volatile("cp.async.cg.shared.global [%0], [%1], 16;" :: "r"(dst), "l"(src))
#define CP_COMMIT()  asm volatile("cp.async.commit_group;" ::: "memory")
#define CP_WAIT1()   asm volatile("cp.async.wait_group 1;" ::: "memory")
#define CP_WAIT0()   asm volatile("cp.async.wait_group 0;" ::: "memory")

__device__ __forceinline__ void ldsm4(unsigned int* r, unsigned int addr){
    asm volatile("ldmatrix.sync.aligned.m8n8.x4.shared.b16 {%0,%1,%2,%3}, [%4];"
        : "=r"(r[0]),"=r"(r[1]),"=r"(r[2]),"=r"(r[3]) : "r"(addr));
}
__device__ __forceinline__ void mma_bf16(float* d, const unsigned int* a, const unsigned int* b){
    asm volatile("mma.sync.aligned.m16n8k16.row.col.f32.bf16.bf16.f32 "
        "{%0,%1,%2,%3}, {%4,%5,%6,%7}, {%8,%9}, {%0,%1,%2,%3};"
        : "+f"(d[0]),"+f"(d[1]),"+f"(d[2]),"+f"(d[3])
        : "r"(a[0]),"r"(a[1]),"r"(a[2]),"r"(a[3]), "r"(b[0]),"r"(b[1]));
}
__device__ __forceinline__ unsigned int fkey(float f){
    unsigned int u = __float_as_uint(f);
    return (u & 0x80000000u) ? ~u : (u | 0x80000000u);
}
__device__ __forceinline__ float unfkey(unsigned int k){
    unsigned int u = (k & 0x80000000u) ? (k & 0x7FFFFFFFu) : ~k;
    return __uint_as_float(u);
}

// ---------------- prep / pool / update kernels ----------------
__global__ void init_kernel(const float* __restrict__ f){
    int i = blockIdx.x*blockDim.x + threadIdx.x;
    if (i < Bb*Nn*Cc){ g_frest[i] = f[i]; g_fhat[i] = 0.0f; }
    if (i == 0) g_loss = 0.0;
}

__global__ void prep_emb_kernel(const float* __restrict__ emb){
    int k = blockIdx.x*blockDim.x + threadIdx.x;
    if (k >= Kk) return;
    const float* e = emb + (size_t)k*Cc;
    float acc = 0.0f;
    #pragma unroll 4
    for (int c=0;c<Cc;c++){
        float v = e[c];
        acc = fmaf(v, v, acc);
        g_emb_h[(size_t)k*Cc + c] = __float2bfloat16_rn(v);
    }
    g_esq[k] = acc;
}

// pool over n; emit fp32 rest + bf16 hi; rsq (sequential order); init per-row state
__global__ void pool_rsq_kernel(int pn){
    __shared__ float sr[256];
    int row = blockIdx.x;          // 0..B*pn-1
    int c   = threadIdx.x;
    int b = row / pn, p = row % pn;
    int s = (p*Nn)/pn;
    int e = ((p+1)*Nn + pn - 1)/pn;
    float w = (float)(1.0/(double)(e-s));
    float acc = 0.0f;
    for (int n=s;n<e;n++) acc = fmaf(w, g_frest[((size_t)b*Nn+n)*Cc + c], acc);
    size_t o = (size_t)row*Cc + c;
    g_rest[o] = acc;
    g_rest_h[o] = __float2bfloat16_rn(acc);
    sr[c] = acc;
    __syncthreads();
    if (c == 0){
        float r = 0.0f;
        #pragma unroll 8
        for (int i=0;i<Cc;i++) r = fmaf(sr[i], sr[i], r);
        g_rsq[row] = r;
        g_dmin[row] = 0xFFFFFFFFu;
        g_ccnt[row] = 0;
        g_win[row] = 0xFFFFFFFFFFFFFFFFull;
    }
}

// ---------------- phase 1: bf16 hi-limb GEMM filter ----------------
// CTA: 256 thr (8 warps, 2x4), tile 128(rows) x 64(codes), K-chunks of 32.
// 3-stage cp.async ring, one __syncthreads per chunk.
// Row stride 80B (64B data + 16B pad) -> conflict-free ldmatrix.
#define KC 32
#define ROWB 80
#define A_STRIDE (128*ROWB)            // 10240
#define B_STRIDE (64*ROWB)             // 5120
#define STAGE_BYTES (A_STRIDE+B_STRIDE)// 15360
#define NSTAGE 3
#define SMEM_GEMM (NSTAGE*STAGE_BYTES) // 46080

__global__ __launch_bounds__(256,3) void gemm_filter_kernel(){
    extern __shared__ char smem[];
    __shared__ unsigned int sdmin[128];
    __shared__ float sthr[128];
    const int tid = threadIdx.x, lane = tid & 31, wid = tid >> 5;
    const int wm = wid >> 2, wn = wid & 3;     // wm: 2 x 64 rows, wn: 4 x 16 cols
    const int row0 = blockIdx.y * 128, k0 = blockIdx.x * 64;
    const unsigned int sbase = smem_u32(smem);

    if (tid < 128) sdmin[tid] = 0xFFFFFFFFu;

    float acc[4][2][4];
    #pragma unroll
    for (int i=0;i<4;i++)
        #pragma unroll
        for (int j=0;j<2;j++)
            #pragma unroll
            for (int q=0;q<4;q++) acc[i][j][q] = 0.0f;

    // cp.async assignment. A: 512 x 16B (all threads, 2 each). B: 256 x 16B (tid<128, 2 each).
    const int arow = tid >> 1, acc0 = (tid & 1) * 2;
    const char* srcA = (const char*)(g_rest_h + (size_t)(row0+arow)*Cc) + acc0*16;
    const unsigned int adst = arow*ROWB + acc0*16;
    const int brow = (tid & 127) >> 1, bcc0 = (tid & 1) * 2;
    const char* srcB = (const char*)(g_emb_h + (size_t)(k0+brow)*Cc) + bcc0*16;
    const unsigned int bdst = A_STRIDE + brow*ROWB + bcc0*16;
    const bool doB = (tid < 128);

    // prologue: chunks 0 and 1 -> stages 0 and 1
    #pragma unroll
    for (int c=0;c<2;c++){
        unsigned int st = sbase + c*STAGE_BYTES;
        CP_ASYNC16(st + adst,      srcA + c*(KC*2));
        CP_ASYNC16(st + adst + 16, srcA + c*(KC*2) + 16);
        if (doB){
            CP_ASYNC16(st + bdst,      srcB + c*(KC*2));
            CP_ASYNC16(st + bdst + 16, srcB + c*(KC*2) + 16);
        }
        CP_COMMIT();
    }

    const int NCHUNK = Cc / KC;   // 8
    int stage = 0;
    for (int c = 0; c < NCHUNK; c++){
        if (c + 1 < NCHUNK) CP_WAIT1(); else CP_WAIT0();
        __syncthreads();   // chunk c visible; all warps done with stage of chunk c-1

        if (c + 2 < NCHUNK){
            int ns = stage + 2; if (ns >= NSTAGE) ns -= NSTAGE;
            unsigned int st = sbase + ns*STAGE_BYTES;
            CP_ASYNC16(st + adst,      srcA + (c+2)*(KC*2));
            CP_ASYNC16(st + adst + 16, srcA + (c+2)*(KC*2) + 16);
            if (doB){
                CP_ASYNC16(st + bdst,      srcB + (c+2)*(KC*2));
                CP_ASYNC16(st + bdst + 16, srcB + (c+2)*(KC*2) + 16);
            }
            CP_COMMIT();
        }

        unsigned int aA = sbase + stage*STAGE_BYTES;
        unsigned int aB = aA + A_STRIDE;

        #pragma unroll
        for (int ks=0; ks<2; ks++){
            unsigned int offA = (unsigned int)((wm*64 + (lane&15))*ROWB + (ks*16 + ((lane>>4)<<3))*2);
            unsigned int offB = (unsigned int)((wn*16 + (lane&7) + ((lane>>4)<<3))*ROWB
                                             + (ks*16 + (((lane>>3)&1)<<3))*2);
            unsigned int bh[4];
            ldsm4(bh, aB + offB);
            unsigned int ah[4][4];
            #pragma unroll
            for (int i=0;i<4;i++) ldsm4(ah[i], aA + offA + i*16*ROWB);
            #pragma unroll
            for (int i=0;i<4;i++)
                #pragma unroll
                for (int j=0;j<2;j++)
                    mma_bf16(acc[i][j], ah[i], bh + 2*j);
        }
        stage++; if (stage >= NSTAGE) stage -= NSTAGE;
    }

    // ---- epilogue pass 1: tile min of d-tilde per row ----
    const int lr = lane >> 2, lc2 = (lane & 3)*2;
    float rsqv[4][2], esv[2][2];
    #pragma unroll
    for (int i=0;i<4;i++){
        rsqv[i][0] = g_rsq[row0 + wm*64 + i*16 + lr];
        rsqv[i][1] = g_rsq[row0 + wm*64 + i*16 + lr + 8];
    }
    #pragma unroll
    for (int j=0;j<2;j++){
        esv[j][0] = g_esq[k0 + wn*16 + j*8 + lc2];
        esv[j][1] = g_esq[k0 + wn*16 + j*8 + lc2 + 1];
    }
    #pragma unroll
    for (int i=0;i<4;i++){
        unsigned int klo = 0xFFFFFFFFu, khi = 0xFFFFFFFFu;
        #pragma unroll
        for (int j=0;j<2;j++){
            unsigned int k00 = fkey(fmaf(-2.0f, acc[i][j][0], rsqv[i][0] + esv[j][0]));
            unsigned int k01 = fkey(fmaf(-2.0f, acc[i][j][1], rsqv[i][0] + esv[j][1]));
            unsigned int k10 = fkey(fmaf(-2.0f, acc[i][j][2], rsqv[i][1] + esv[j][0]));
            unsigned int k11 = fkey(fmaf(-2.0f, acc[i][j][3], rsqv[i][1] + esv[j][1]));
            klo = min(klo, min(k00,k01));
            khi = min(khi, min(k10,k11));
        }
        #pragma unroll
        for (int off=1; off<=2; off<<=1){
            klo = min(klo, __shfl_xor_sync(0xffffffffu, klo, off));
            khi = min(khi, __shfl_xor_sync(0xffffffffu, khi, off));
        }
        if ((lane & 3) == 0){
            atomicMin(&sdmin[wm*64 + i*16 + lr],     klo);
            atomicMin(&sdmin[wm*64 + i*16 + lr + 8], khi);
        }
    }
    __syncthreads();

    // ---- global min + threshold ----
    if (tid < 128){
        unsigned int old = atomicMin(&g_dmin[row0 + tid], sdmin[tid]);
        unsigned int m = min(old, sdmin[tid]);
        float dm = unfkey(m);
        float rsq = g_rsq[row0 + tid];
        sthr[tid] = dm + (rsq*4e-7f + 8e-5f);
    }
    __syncthreads();

    // ---- epilogue pass 2: append candidates below threshold ----
    #pragma unroll
    for (int i=0;i<4;i++){
        int rlo = wm*64 + i*16 + lr;
        int rhi = rlo + 8;
        float tlo = sthr[rlo], thi = sthr[rhi];
        #pragma unroll
        for (int j=0;j<2;j++){
            int col = k0 + wn*16 + j*8 + lc2;
            float d00 = fmaf(-2.0f, acc[i][j][0], rsqv[i][0] + esv[j][0]);
            float d01 = fmaf(-2.0f, acc[i][j][1], rsqv[i][0] + esv[j][1]);
            float d10 = fmaf(-2.0f, acc[i][j][2], rsqv[i][1] + esv[j][0]);
            float d11 = fmaf(-2.0f, acc[i][j][3], rsqv[i][1] + esv[j][1]);
            if (d00 < tlo){ int s = atomicAdd(&g_ccnt[row0+rlo], 1); if (s < MAXC) g_cand[(size_t)(row0+rlo)*MAXC + s] = col; }
            if (d01 < tlo){ int s = atomicAdd(&g_ccnt[row0+rlo], 1); if (s < MAXC) g_cand[(size_t)(row0+rlo)*MAXC + s] = col+1; }
            if (d10 < thi){ int s = atomicAdd(&g_ccnt[row0+rhi], 1); if (s < MAXC) g_cand[(size_t)(row0+rhi)*MAXC + s] = col; }
            if (d11 < thi){ int s = atomicAdd(&g_ccnt[row0+rhi], 1); if (s < MAXC) g_cand[(size_t)(row0+rhi)*MAXC + s] = col+1; }
        }
    }
}

// ---------------- phase 2: exact rescore of candidates ----------------
__global__ void rescore_kernel(const float* __restrict__ emb){
    __shared__ float srest[256];
    int row = blockIdx.x;
    int tid = threadIdx.x;
    srest[tid]       = g_rest[(size_t)row*Cc + tid];
    srest[tid + 128] = g_rest[(size_t)row*Cc + tid + 128];
    __syncthreads();
    int cnt = g_ccnt[row];
    if (cnt > MAXC) cnt = MAXC;
    float rsq = g_rsq[row];
    for (int t = tid; t < cnt; t += 128){
        int k = g_cand[(size_t)row*MAXC + t];
        const float* e = emb + (size_t)k*Cc;
        float acc = 0.0f;
        #pragma unroll 8
        for (int c=0;c<Cc;c++) acc = fmaf(srest[c], __ldg(e + c), acc);
        float d = fmaf(-2.0f, acc, rsq + g_esq[k]);
        unsigned long long key = ((unsigned long long)fkey(d) << 32) | (unsigned int)k;
        atomicMin(&g_win[row], key);
    }
}

// ---------------- winner gather / residual update / loss ----------------
__global__ void update_kernel(const float* __restrict__ f, const float* __restrict__ emb, int pn){
    __shared__ double sred[256];
    int bn = blockIdx.x;
    int b = bn >> 4, n = bn & 15;
    int c = threadIdx.x;

    float h;
    if (pn == Nn){
        int k0 = (int)(g_win[(size_t)b*pn + n] & 0xFFFFFFFFull);
        h = emb[(size_t)k0*Cc + c];
    } else {
        double scale = (double)pn / 16.0;
        double pos = ((double)n + 0.5)*scale - 0.5;
        if (pos < 0.0) pos = 0.0;
        int i0 = (int)floor(pos);
        if (i0 > pn-1) i0 = pn-1;
        double frac = pos - (double)i0;
        int i1 = i0 + 1; if (i1 > pn-1) i1 = pn-1;
        float w0 = (float)(1.0 - frac);
        int k0 = (int)(g_win[(size_t)b*pn + i0] & 0xFFFFFFFFull);
        if (i1 == i0){
            float w = (float)((double)w0 + frac);
            h = w * emb[(size_t)k0*Cc + c];
        } else {
            float w1 = (float)frac;
            int k1 = (int)(g_win[(size_t)b*pn + i1] & 0xFFFFFFFFull);
            h = fmaf(w1, emb[(size_t)k1*Cc + c], w0 * emb[(size_t)k0*Cc + c]);
        }
    }

    size_t idx = (size_t)bn*Cc + c;
    float fh = g_fhat[idx] + h;
    g_fhat[idx] = fh;
    g_frest[idx] = g_frest[idx] - h;
    float t = fh - f[idx];
    sred[c] = (double)t * (double)t;
    __syncthreads();
    for (int s=128;s>0;s>>=1){
        if (c < s) sred[c] += sred[c+s];
        __syncthreads();
    }
    if (c == 0) atomicAdd(&g_loss, sred[0]);
}

__global__ void finalize_kernel(float* __restrict__ out){
    int i = blockIdx.x*blockDim.x + threadIdx.x;
    if (i < Bb*Nn*Cc) out[i] = g_fhat[i];
    if (i == 0){
        double S = g_loss / (double)(Bb*Nn*Cc);
        out[Bb*Nn*Cc]     = (float)(0.25 * S / 16.0);   // commit
        out[Bb*Nn*Cc + 1] = (float)(S / 16.0);          // qlat
    }
}

extern "C" void kernel_launch(void* const* d_in, const int* in_sizes, int n_in,
                              void* d_out, int out_size){
    const float* f   = (const float*)d_in[0];
    const float* emb = (const float*)d_in[1];
    float* out = (float*)d_out;

    cudaFuncSetAttribute(gemm_filter_kernel, cudaFuncAttributeMaxDynamicSharedMemorySize, SMEM_GEMM);

    init_kernel<<<(Bb*Nn*Cc + 255)/256, 256>>>(f);
    prep_emb_kernel<<<(Kk + 255)/256, 256>>>(emb);

    for (int pn=1; pn<=Nn; pn++){
        int M = Bb*pn;
        pool_rsq_kernel<<<M, 256>>>(pn);
        dim3 grid(Kk/64, M/128);
        gemm_filter_kernel<<<grid, 256, SMEM_GEMM>>>();
        rescore_kernel<<<M, 128>>>(emb);
        update_kernel<<<Bb*Nn, 256>>>(f, emb, pn);
    }
    finalize_kernel<<<(Bb*Nn*Cc + 255)/256, 256>>>(out);
}

// round 11
// speedup vs baseline: 1.7735x; 1.7735x over previous
#include <cuda_runtime.h>
#include <cuda_bf16.h>
#include <stdint.h>
#include <math.h>

#define Bb 512
#define Nn 16
#define Cc 256
#define Kk 8192
#define MAXC 512

// ---------------- device globals (no allocations allowed) ----------------
__device__ float g_frest[Bb*Nn*Cc];
__device__ float g_fhat [Bb*Nn*Cc];
__device__ float g_rest [Bb*Nn*Cc];
__device__ __nv_bfloat16 g_rest_h[Bb*Nn*Cc];
__device__ __nv_bfloat16 g_emb_h[Kk*Cc];
__device__ float g_rsq  [Bb*Nn];
__device__ float g_esq  [Kk];
__device__ unsigned int g_dmin[Bb*Nn];          // fkey32 of min d-tilde
__device__ int g_ccnt[Bb*Nn];
__device__ int g_cand[Bb*Nn*MAXC];
__device__ unsigned long long g_win[Bb*Nn];
__device__ double g_loss;

// ---------------- helpers ----------------
__device__ __forceinline__ unsigned int smem_u32(const void* p){
    unsigned int a;
    asm("{ .reg .u64 t; cvta.to.shared.u64 t, %1; cvt.u32.u64 %0, t; }" : "=r"(a) : "l"(p));
    return a;
}
#define CP_ASYNC16(dst,src) asm volatile("cp.async.cg.shared.global [%0], [%1], 16;" :: "r"(dst), "l"(src))
#define CP_COMMIT()  asm volatile("cp.async.commit_group;" ::: "memory")
#define CP_WAIT1()   asm volatile("cp.async.wait_group 1;" ::: "memory")
#define CP_WAIT0()   asm volatile("cp.async.wait_group 0;" ::: "memory")

__device__ __forceinline__ void ldsm4(unsigned int* r, unsigned int addr){
    asm volatile("ldmatrix.sync.aligned.m8n8.x4.shared.b16 {%0,%1,%2,%3}, [%4];"
        : "=r"(r[0]),"=r"(r[1]),"=r"(r[2]),"=r"(r[3]) : "r"(addr));
}
__device__ __forceinline__ void mma_bf16(float* d, const unsigned int* a, const unsigned int* b){
    asm volatile("mma.sync.aligned.m16n8k16.row.col.f32.bf16.bf16.f32 "
        "{%0,%1,%2,%3}, {%4,%5,%6,%7}, {%8,%9}, {%0,%1,%2,%3};"
        : "+f"(d[0]),"+f"(d[1]),"+f"(d[2]),"+f"(d[3])
        : "r"(a[0]),"r"(a[1]),"r"(a[2]),"r"(a[3]), "r"(b[0]),"r"(b[1]));
}
__device__ __forceinline__ unsigned int fkey(float f){
    unsigned int u = __float_as_uint(f);
    return (u & 0x80000000u) ? ~u : (u | 0x80000000u);
}
__device__ __forceinline__ float unfkey(unsigned int k){
    unsigned int u = (k & 0x80000000u) ? (k & 0x7FFFFFFFu) : ~k;
    return __uint_as_float(u);
}

// ---------------- prep / pool / update kernels ----------------
__global__ void init_kernel(const float* __restrict__ f){
    int i = blockIdx.x*blockDim.x + threadIdx.x;
    if (i < Bb*Nn*Cc){ g_frest[i] = f[i]; g_fhat[i] = 0.0f; }
    if (i == 0) g_loss = 0.0;
}

__global__ void prep_emb_kernel(const float* __restrict__ emb){
    int k = blockIdx.x*blockDim.x + threadIdx.x;
    if (k >= Kk) return;
    const float* e = emb + (size_t)k*Cc;
    float acc = 0.0f;
    #pragma unroll 4
    for (int c=0;c<Cc;c++){
        float v = e[c];
        acc = fmaf(v, v, acc);
        g_emb_h[(size_t)k*Cc + c] = __float2bfloat16_rn(v);
    }
    g_esq[k] = acc;
}

// pool over n; emit fp32 rest + bf16 hi; rsq (sequential order); init per-row state
__global__ void pool_rsq_kernel(int pn){
    __shared__ float sr[256];
    int row = blockIdx.x;          // 0..B*pn-1
    int c   = threadIdx.x;
    int b = row / pn, p = row % pn;
    int s = (p*Nn)/pn;
    int e = ((p+1)*Nn + pn - 1)/pn;
    float w = (float)(1.0/(double)(e-s));
    float acc = 0.0f;
    for (int n=s;n<e;n++) acc = fmaf(w, g_frest[((size_t)b*Nn+n)*Cc + c], acc);
    size_t o = (size_t)row*Cc + c;
    g_rest[o] = acc;
    g_rest_h[o] = __float2bfloat16_rn(acc);
    sr[c] = acc;
    __syncthreads();
    if (c == 0){
        float r = 0.0f;
        #pragma unroll 8
        for (int i=0;i<Cc;i++) r = fmaf(sr[i], sr[i], r);
        g_rsq[row] = r;
        g_dmin[row] = 0xFFFFFFFFu;
        g_ccnt[row] = 0;
        g_win[row] = 0xFFFFFFFFFFFFFFFFull;
    }
}

// ---------------- phase 1: bf16 hi-limb GEMM filter ----------------
// CTA: 512 thr (16 warps, 4x4), tile 128(rows) x 128(codes), K-chunks of 32.
// Warp tile 32x32. 3-stage cp.async ring, one __syncthreads per chunk.
// Row stride 80B (64B data + 16B pad) -> conflict-free ldmatrix.
#define KC 32
#define ROWB 80
#define REG_STRIDE (128*ROWB)          // 10240
#define STAGE_BYTES (2*REG_STRIDE)     // 20480 (A region + B region)
#define NSTAGE 3
#define SMEM_GEMM (NSTAGE*STAGE_BYTES) // 61440

__global__ __launch_bounds__(512,2) void gemm_filter_kernel(){
    extern __shared__ char smem[];
    __shared__ unsigned int sdmin[128];
    __shared__ float sthr[128];
    const int tid = threadIdx.x, lane = tid & 31, wid = tid >> 5;
    const int wm = wid >> 2, wn = wid & 3;     // 4 x 32 rows, 4 x 32 cols
    const int row0 = blockIdx.y * 128, k0 = blockIdx.x * 128;
    const unsigned int sbase = smem_u32(smem);

    if (tid < 128) sdmin[tid] = 0xFFFFFFFFu;

    float acc[2][4][4];
    #pragma unroll
    for (int i=0;i<2;i++)
        #pragma unroll
        for (int j=0;j<4;j++)
            #pragma unroll
            for (int q=0;q<4;q++) acc[i][j][q] = 0.0f;

    // cp.async: A 512 x 16B chunks, B 512 x 16B chunks; 1 each per thread.
    const int arow = tid >> 2, apos = (tid & 3);
    const char* srcA = (const char*)(g_rest_h + (size_t)(row0+arow)*Cc) + apos*16;
    const char* srcB = (const char*)(g_emb_h  + (size_t)(k0 +arow)*Cc) + apos*16;
    const unsigned int adst = arow*ROWB + apos*16;

    // prologue: chunks 0 and 1 -> stages 0 and 1
    #pragma unroll
    for (int c=0;c<2;c++){
        unsigned int st = sbase + c*STAGE_BYTES;
        CP_ASYNC16(st + adst,              srcA + c*(KC*2));
        CP_ASYNC16(st + adst + REG_STRIDE, srcB + c*(KC*2));
        CP_COMMIT();
    }

    const int NCHUNK = Cc / KC;   // 8
    int stage = 0;
    for (int c = 0; c < NCHUNK; c++){
        if (c + 1 < NCHUNK) CP_WAIT1(); else CP_WAIT0();
        __syncthreads();   // chunk c visible; all warps done with stage of chunk c-1

        if (c + 2 < NCHUNK){
            int ns = stage + 2; if (ns >= NSTAGE) ns -= NSTAGE;
            unsigned int st = sbase + ns*STAGE_BYTES;
            CP_ASYNC16(st + adst,              srcA + (c+2)*(KC*2));
            CP_ASYNC16(st + adst + REG_STRIDE, srcB + (c+2)*(KC*2));
            CP_COMMIT();
        }

        unsigned int aA = sbase + stage*STAGE_BYTES;
        unsigned int aB = aA + REG_STRIDE;

        #pragma unroll
        for (int ks=0; ks<2; ks++){
            unsigned int offA = (unsigned int)((wm*32 + (lane&15))*ROWB + (ks*16 + ((lane>>4)<<3))*2);
            unsigned int offB = (unsigned int)((wn*32 + (lane&7) + ((lane>>4)<<3))*ROWB
                                             + (ks*16 + (((lane>>3)&1)<<3))*2);
            unsigned int bh[8];
            ldsm4(bh+0, aB + offB); ldsm4(bh+4, aB + offB + 16*ROWB);
            unsigned int ah[2][4];
            #pragma unroll
            for (int i=0;i<2;i++) ldsm4(ah[i], aA + offA + i*16*ROWB);
            #pragma unroll
            for (int i=0;i<2;i++)
                #pragma unroll
                for (int j=0;j<4;j++)
                    mma_bf16(acc[i][j], ah[i], bh + 2*j);
        }
        stage++; if (stage >= NSTAGE) stage -= NSTAGE;
    }

    // ---- epilogue pass 1: tile min of d-tilde per row ----
    const int lr = lane >> 2, lc2 = (lane & 3)*2;
    float rsqv[2][2], esv[4][2];
    #pragma unroll
    for (int i=0;i<2;i++){
        rsqv[i][0] = g_rsq[row0 + wm*32 + i*16 + lr];
        rsqv[i][1] = g_rsq[row0 + wm*32 + i*16 + lr + 8];
    }
    #pragma unroll
    for (int j=0;j<4;j++){
        esv[j][0] = g_esq[k0 + wn*32 + j*8 + lc2];
        esv[j][1] = g_esq[k0 + wn*32 + j*8 + lc2 + 1];
    }
    #pragma unroll
    for (int i=0;i<2;i++){
        unsigned int klo = 0xFFFFFFFFu, khi = 0xFFFFFFFFu;
        #pragma unroll
        for (int j=0;j<4;j++){
            unsigned int k00 = fkey(fmaf(-2.0f, acc[i][j][0], rsqv[i][0] + esv[j][0]));
            unsigned int k01 = fkey(fmaf(-2.0f, acc[i][j][1], rsqv[i][0] + esv[j][1]));
            unsigned int k10 = fkey(fmaf(-2.0f, acc[i][j][2], rsqv[i][1] + esv[j][0]));
            unsigned int k11 = fkey(fmaf(-2.0f, acc[i][j][3], rsqv[i][1] + esv[j][1]));
            klo = min(klo, min(k00,k01));
            khi = min(khi, min(k10,k11));
        }
        #pragma unroll
        for (int off=1; off<=2; off<<=1){
            klo = min(klo, __shfl_xor_sync(0xffffffffu, klo, off));
            khi = min(khi, __shfl_xor_sync(0xffffffffu, khi, off));
        }
        if ((lane & 3) == 0){
            atomicMin(&sdmin[wm*32 + i*16 + lr],     klo);
            atomicMin(&sdmin[wm*32 + i*16 + lr + 8], khi);
        }
    }
    __syncthreads();

    // ---- global min + threshold ----
    if (tid < 128){
        unsigned int old = atomicMin(&g_dmin[row0 + tid], sdmin[tid]);
        unsigned int m = min(old, sdmin[tid]);
        float dm = unfkey(m);
        float rsq = g_rsq[row0 + tid];
        sthr[tid] = dm + (rsq*4e-7f + 8e-5f);
    }
    __syncthreads();

    // ---- epilogue pass 2: append candidates below threshold ----
    #pragma unroll
    for (int i=0;i<2;i++){
        int rlo = wm*32 + i*16 + lr;
        int rhi = rlo + 8;
        float tlo = sthr[rlo], thi = sthr[rhi];
        #pragma unroll
        for (int j=0;j<4;j++){
            int col = k0 + wn*32 + j*8 + lc2;
            float d00 = fmaf(-2.0f, acc[i][j][0], rsqv[i][0] + esv[j][0]);
            float d01 = fmaf(-2.0f, acc[i][j][1], rsqv[i][0] + esv[j][1]);
            float d10 = fmaf(-2.0f, acc[i][j][2], rsqv[i][1] + esv[j][0]);
            float d11 = fmaf(-2.0f, acc[i][j][3], rsqv[i][1] + esv[j][1]);
            if (d00 < tlo){ int s = atomicAdd(&g_ccnt[row0+rlo], 1); if (s < MAXC) g_cand[(size_t)(row0+rlo)*MAXC + s] = col; }
            if (d01 < tlo){ int s = atomicAdd(&g_ccnt[row0+rlo], 1); if (s < MAXC) g_cand[(size_t)(row0+rlo)*MAXC + s] = col+1; }
            if (d10 < thi){ int s = atomicAdd(&g_ccnt[row0+rhi], 1); if (s < MAXC) g_cand[(size_t)(row0+rhi)*MAXC + s] = col; }
            if (d11 < thi){ int s = atomicAdd(&g_ccnt[row0+rhi], 1); if (s < MAXC) g_cand[(size_t)(row0+rhi)*MAXC + s] = col+1; }
        }
    }
}

// ---------------- phase 2: exact rescore of candidates ----------------
__global__ void rescore_kernel(const float* __restrict__ emb){
    __shared__ float srest[256];
    int row = blockIdx.x;
    int tid = threadIdx.x;
    srest[tid]       = g_rest[(size_t)row*Cc + tid];
    srest[tid + 128] = g_rest[(size_t)row*Cc + tid + 128];
    __syncthreads();
    int cnt = g_ccnt[row];
    if (cnt > MAXC) cnt = MAXC;
    float rsq = g_rsq[row];
    for (int t = tid; t < cnt; t += 128){
        int k = g_cand[(size_t)row*MAXC + t];
        const float* e = emb + (size_t)k*Cc;
        float acc = 0.0f;
        #pragma unroll 8
        for (int c=0;c<Cc;c++) acc = fmaf(srest[c], __ldg(e + c), acc);
        float d = fmaf(-2.0f, acc, rsq + g_esq[k]);
        unsigned long long key = ((unsigned long long)fkey(d) << 32) | (unsigned int)k;
        atomicMin(&g_win[row], key);
    }
}

// ---------------- winner gather / residual update / loss ----------------
__global__ void update_kernel(const float* __restrict__ f, const float* __restrict__ emb, int pn){
    __shared__ double sred[256];
    int bn = blockIdx.x;
    int b = bn >> 4, n = bn & 15;
    int c = threadIdx.x;

    float h;
    if (pn == Nn){
        int k0 = (int)(g_win[(size_t)b*pn + n] & 0xFFFFFFFFull);
        h = emb[(size_t)k0*Cc + c];
    } else {
        double scale = (double)pn / 16.0;
        double pos = ((double)n + 0.5)*scale - 0.5;
        if (pos < 0.0) pos = 0.0;
        int i0 = (int)floor(pos);
        if (i0 > pn-1) i0 = pn-1;
        double frac = pos - (double)i0;
        int i1 = i0 + 1; if (i1 > pn-1) i1 = pn-1;
        float w0 = (float)(1.0 - frac);
        int k0 = (int)(g_win[(size_t)b*pn + i0] & 0xFFFFFFFFull);
        if (i1 == i0){
            float w = (float)((double)w0 + frac);
            h = w * emb[(size_t)k0*Cc + c];
        } else {
            float w1 = (float)frac;
            int k1 = (int)(g_win[(size_t)b*pn + i1] & 0xFFFFFFFFull);
            h = fmaf(w1, emb[(size_t)k1*Cc + c], w0 * emb[(size_t)k0*Cc + c]);
        }
    }

    size_t idx = (size_t)bn*Cc + c;
    float fh = g_fhat[idx] + h;
    g_fhat[idx] = fh;
    g_frest[idx] = g_frest[idx] - h;
    float t = fh - f[idx];
    sred[c] = (double)t * (double)t;
    __syncthreads();
    for (int s=128;s>0;s>>=1){
        if (c < s) sred[c] += sred[c+s];
        __syncthreads();
    }
    if (c == 0) atomicAdd(&g_loss, sred[0]);
}

__global__ void finalize_kernel(float* __restrict__ out){
    int i = blockIdx.x*blockDim.x + threadIdx.x;
    if (i < Bb*Nn*Cc) out[i] = g_fhat[i];
    if (i == 0){
        double S = g_loss / (double)(Bb*Nn*Cc);
        out[Bb*Nn*Cc]     = (float)(0.25 * S / 16.0);   // commit
        out[Bb*Nn*Cc + 1] = (float)(S / 16.0);          // qlat
    }
}

extern "C" void kernel_launch(void* const* d_in, const int* in_sizes, int n_in,
                              void* d_out, int out_size){
    const float* f   = (const float*)d_in[0];
    const float* emb = (const float*)d_in[1];
    float* out = (float*)d_out;

    cudaFuncSetAttribute(gemm_filter_kernel, cudaFuncAttributeMaxDynamicSharedMemorySize, SMEM_GEMM);

    init_kernel<<<(Bb*Nn*Cc + 255)/256, 256>>>(f);
    prep_emb_kernel<<<(Kk + 255)/256, 256>>>(emb);

    for (int pn=1; pn<=Nn; pn++){
        int M = Bb*pn;
        pool_rsq_kernel<<<M, 256>>>(pn);
        dim3 grid(Kk/128, M/128);
        gemm_filter_kernel<<<grid, 512, SMEM_GEMM>>>();
        rescore_kernel<<<M, 128>>>(emb);
        update_kernel<<<Bb*Nn, 256>>>(f, emb, pn);
    }
    finalize_kernel<<<(Bb*Nn*Cc + 255)/256, 256>>>(out);
}

// round 12
// speedup vs baseline: 1.7913x; 1.0101x over previous
#include <cuda_runtime.h>
#include <cuda_bf16.h>
#include <stdint.h>
#include <math.h>

#define Bb 512
#define Nn 16
#define Cc 256
#define Kk 8192
#define MAXC 512

// ---------------- device globals (no allocations allowed) ----------------
__device__ float g_frest[Bb*Nn*Cc];
__device__ float g_fhat [Bb*Nn*Cc];
__device__ float g_rest [Bb*Nn*Cc];
__device__ __nv_bfloat16 g_rest_h[Bb*Nn*Cc];
__device__ __nv_bfloat16 g_emb_h[Kk*Cc];
__device__ float g_rsq  [Bb*Nn];
__device__ float g_esq  [Kk];
__device__ unsigned int g_dmin[Bb*Nn];          // fkey32 of min d-tilde
__device__ int g_ccnt[Bb*Nn];
__device__ int g_cand[Bb*Nn*MAXC];
__device__ unsigned long long g_win[Bb*Nn];
__device__ double g_loss;

// ---------------- helpers ----------------
__device__ __forceinline__ unsigned int smem_u32(const void* p){
    unsigned int a;
    asm("{ .reg .u64 t; cvta.to.shared.u64 t, %1; cvt.u32.u64 %0, t; }" : "=r"(a) : "l"(p));
    return a;
}
#define CP_ASYNC16(dst,src) asm volatile("cp.async.cg.shared.global [%0], [%1], 16;" :: "r"(dst), "l"(src))
#define CP_COMMIT()  asm volatile("cp.async.commit_group;" ::: "memory")
#define CP_WAIT1()   asm volatile("cp.async.wait_group 1;" ::: "memory")
#define CP_WAIT0()   asm volatile("cp.async.wait_group 0;" ::: "memory")

__device__ __forceinline__ void ldsm4(unsigned int* r, unsigned int addr){
    asm volatile("ldmatrix.sync.aligned.m8n8.x4.shared.b16 {%0,%1,%2,%3}, [%4];"
        : "=r"(r[0]),"=r"(r[1]),"=r"(r[2]),"=r"(r[3]) : "r"(addr));
}
__device__ __forceinline__ void mma_bf16(float* d, const unsigned int* a, const unsigned int* b){
    asm volatile("mma.sync.aligned.m16n8k16.row.col.f32.bf16.bf16.f32 "
        "{%0,%1,%2,%3}, {%4,%5,%6,%7}, {%8,%9}, {%0,%1,%2,%3};"
        : "+f"(d[0]),"+f"(d[1]),"+f"(d[2]),"+f"(d[3])
        : "r"(a[0]),"r"(a[1]),"r"(a[2]),"r"(a[3]), "r"(b[0]),"r"(b[1]));
}
__device__ __forceinline__ unsigned int fkey(float f){
    unsigned int u = __float_as_uint(f);
    return (u & 0x80000000u) ? ~u : (u | 0x80000000u);
}
__device__ __forceinline__ float unfkey(unsigned int k){
    unsigned int u = (k & 0x80000000u) ? (k & 0x7FFFFFFFu) : ~k;
    return __uint_as_float(u);
}

// ---------------- prep / pool / update kernels ----------------
__global__ void init_kernel(const float* __restrict__ f){
    int i = blockIdx.x*blockDim.x + threadIdx.x;
    if (i < Bb*Nn*Cc){ g_frest[i] = f[i]; g_fhat[i] = 0.0f; }
    if (i == 0) g_loss = 0.0;
}

__global__ void prep_emb_kernel(const float* __restrict__ emb){
    int k = blockIdx.x*blockDim.x + threadIdx.x;
    if (k >= Kk) return;
    const float* e = emb + (size_t)k*Cc;
    float acc = 0.0f;
    #pragma unroll 4
    for (int c=0;c<Cc;c++){
        float v = e[c];
        acc = fmaf(v, v, acc);
        g_emb_h[(size_t)k*Cc + c] = __float2bfloat16_rn(v);
    }
    g_esq[k] = acc;
}

// pool over n; emit fp32 rest + bf16 hi; rsq (sequential order); init per-row state
__global__ void pool_rsq_kernel(int pn){
    __shared__ float sr[256];
    int row = blockIdx.x;          // 0..B*pn-1
    int c   = threadIdx.x;
    int b = row / pn, p = row % pn;
    int s = (p*Nn)/pn;
    int e = ((p+1)*Nn + pn - 1)/pn;
    float w = (float)(1.0/(double)(e-s));
    float acc = 0.0f;
    for (int n=s;n<e;n++) acc = fmaf(w, g_frest[((size_t)b*Nn+n)*Cc + c], acc);
    size_t o = (size_t)row*Cc + c;
    g_rest[o] = acc;
    g_rest_h[o] = __float2bfloat16_rn(acc);
    sr[c] = acc;
    __syncthreads();
    if (c == 0){
        float r = 0.0f;
        #pragma unroll 8
        for (int i=0;i<Cc;i++) r = fmaf(sr[i], sr[i], r);
        g_rsq[row] = r;
        g_dmin[row] = 0xFFFFFFFFu;
        g_ccnt[row] = 0;
        g_win[row] = 0xFFFFFFFFFFFFFFFFull;
    }
}

// ---------------- phase 1: bf16 hi-limb GEMM filter ----------------
// CTA: 512 thr (16 warps, 4x4), tile 128(rows) x 128(codes), K-chunks of 64.
// Warp tile 32x32. 3-stage cp.async ring, one __syncthreads per chunk (4 chunks).
// Row stride 144B (128B data + 16B pad); 144/16=9, gcd(9,8)=1 -> conflict-free ldmatrix.
#define KC 64
#define ROWB 144
#define REG_STRIDE (128*ROWB)          // 18432
#define STAGE_BYTES (2*REG_STRIDE)     // 36864 (A region + B region)
#define NSTAGE 3
#define SMEM_GEMM (NSTAGE*STAGE_BYTES) // 110592

__global__ __launch_bounds__(512,2) void gemm_filter_kernel(){
    extern __shared__ char smem[];
    __shared__ unsigned int sdmin[128];
    __shared__ float sthr[128];
    const int tid = threadIdx.x, lane = tid & 31, wid = tid >> 5;
    const int wm = wid >> 2, wn = wid & 3;     // 4 x 32 rows, 4 x 32 cols
    const int row0 = blockIdx.y * 128, k0 = blockIdx.x * 128;
    const unsigned int sbase = smem_u32(smem);

    if (tid < 128) sdmin[tid] = 0xFFFFFFFFu;

    float acc[2][4][4];
    #pragma unroll
    for (int i=0;i<2;i++)
        #pragma unroll
        for (int j=0;j<4;j++)
            #pragma unroll
            for (int q=0;q<4;q++) acc[i][j][q] = 0.0f;

    // cp.async: per stage, A region 128 rows x 128B = 1024 x 16B, same for B.
    // 512 threads -> each does 2 A-chunks + 2 B-chunks (adjacent 16B).
    const int arow = tid >> 2, apos = (tid & 3) * 2;   // apos in 16B units: 0,2,4,6
    const char* srcA = (const char*)(g_rest_h + (size_t)(row0+arow)*Cc) + apos*16;
    const char* srcB = (const char*)(g_emb_h  + (size_t)(k0 +arow)*Cc) + apos*16;
    const unsigned int adst = arow*ROWB + apos*16;

    // prologue: chunks 0 and 1 -> stages 0 and 1
    #pragma unroll
    for (int c=0;c<2;c++){
        unsigned int st = sbase + c*STAGE_BYTES;
        CP_ASYNC16(st + adst,                   srcA + c*(KC*2));
        CP_ASYNC16(st + adst + 16,              srcA + c*(KC*2) + 16);
        CP_ASYNC16(st + adst + REG_STRIDE,      srcB + c*(KC*2));
        CP_ASYNC16(st + adst + REG_STRIDE + 16, srcB + c*(KC*2) + 16);
        CP_COMMIT();
    }

    const int NCHUNK = Cc / KC;   // 4
    int stage = 0;
    for (int c = 0; c < NCHUNK; c++){
        if (c + 1 < NCHUNK) CP_WAIT1(); else CP_WAIT0();
        __syncthreads();   // chunk c visible; all warps done with stage of chunk c-1

        if (c + 2 < NCHUNK){
            int ns = stage + 2; if (ns >= NSTAGE) ns -= NSTAGE;
            unsigned int st = sbase + ns*STAGE_BYTES;
            CP_ASYNC16(st + adst,                   srcA + (c+2)*(KC*2));
            CP_ASYNC16(st + adst + 16,              srcA + (c+2)*(KC*2) + 16);
            CP_ASYNC16(st + adst + REG_STRIDE,      srcB + (c+2)*(KC*2));
            CP_ASYNC16(st + adst + REG_STRIDE + 16, srcB + (c+2)*(KC*2) + 16);
            CP_COMMIT();
        }

        unsigned int aA = sbase + stage*STAGE_BYTES;
        unsigned int aB = aA + REG_STRIDE;

        #pragma unroll
        for (int ks=0; ks<4; ks++){
            unsigned int offA = (unsigned int)((wm*32 + (lane&15))*ROWB + (ks*16 + ((lane>>4)<<3))*2);
            unsigned int offB = (unsigned int)((wn*32 + (lane&7) + ((lane>>4)<<3))*ROWB
                                             + (ks*16 + (((lane>>3)&1)<<3))*2);
            unsigned int bh[8];
            ldsm4(bh+0, aB + offB); ldsm4(bh+4, aB + offB + 16*ROWB);
            unsigned int ah[2][4];
            #pragma unroll
            for (int i=0;i<2;i++) ldsm4(ah[i], aA + offA + i*16*ROWB);
            #pragma unroll
            for (int i=0;i<2;i++)
                #pragma unroll
                for (int j=0;j<4;j++)
                    mma_bf16(acc[i][j], ah[i], bh + 2*j);
        }
        stage++; if (stage >= NSTAGE) stage -= NSTAGE;
    }

    // ---- epilogue pass 1: tile min of d-tilde per row ----
    const int lr = lane >> 2, lc2 = (lane & 3)*2;
    float rsqv[2][2], esv[4][2];
    #pragma unroll
    for (int i=0;i<2;i++){
        rsqv[i][0] = g_rsq[row0 + wm*32 + i*16 + lr];
        rsqv[i][1] = g_rsq[row0 + wm*32 + i*16 + lr + 8];
    }
    #pragma unroll
    for (int j=0;j<4;j++){
        esv[j][0] = g_esq[k0 + wn*32 + j*8 + lc2];
        esv[j][1] = g_esq[k0 + wn*32 + j*8 + lc2 + 1];
    }
    #pragma unroll
    for (int i=0;i<2;i++){
        unsigned int klo = 0xFFFFFFFFu, khi = 0xFFFFFFFFu;
        #pragma unroll
        for (int j=0;j<4;j++){
            unsigned int k00 = fkey(fmaf(-2.0f, acc[i][j][0], rsqv[i][0] + esv[j][0]));
            unsigned int k01 = fkey(fmaf(-2.0f, acc[i][j][1], rsqv[i][0] + esv[j][1]));
            unsigned int k10 = fkey(fmaf(-2.0f, acc[i][j][2], rsqv[i][1] + esv[j][0]));
            unsigned int k11 = fkey(fmaf(-2.0f, acc[i][j][3], rsqv[i][1] + esv[j][1]));
            klo = min(klo, min(k00,k01));
            khi = min(khi, min(k10,k11));
        }
        #pragma unroll
        for (int off=1; off<=2; off<<=1){
            klo = min(klo, __shfl_xor_sync(0xffffffffu, klo, off));
            khi = min(khi, __shfl_xor_sync(0xffffffffu, khi, off));
        }
        if ((lane & 3) == 0){
            atomicMin(&sdmin[wm*32 + i*16 + lr],     klo);
            atomicMin(&sdmin[wm*32 + i*16 + lr + 8], khi);
        }
    }
    __syncthreads();

    // ---- global min + threshold ----
    if (tid < 128){
        unsigned int old = atomicMin(&g_dmin[row0 + tid], sdmin[tid]);
        unsigned int m = min(old, sdmin[tid]);
        float dm = unfkey(m);
        float rsq = g_rsq[row0 + tid];
        sthr[tid] = dm + (rsq*4e-7f + 8e-5f);
    }
    __syncthreads();

    // ---- epilogue pass 2: append candidates below threshold ----
    #pragma unroll
    for (int i=0;i<2;i++){
        int rlo = wm*32 + i*16 + lr;
        int rhi = rlo + 8;
        float tlo = sthr[rlo], thi = sthr[rhi];
        #pragma unroll
        for (int j=0;j<4;j++){
            int col = k0 + wn*32 + j*8 + lc2;
            float d00 = fmaf(-2.0f, acc[i][j][0], rsqv[i][0] + esv[j][0]);
            float d01 = fmaf(-2.0f, acc[i][j][1], rsqv[i][0] + esv[j][1]);
            float d10 = fmaf(-2.0f, acc[i][j][2], rsqv[i][1] + esv[j][0]);
            float d11 = fmaf(-2.0f, acc[i][j][3], rsqv[i][1] + esv[j][1]);
            if (d00 < tlo){ int s = atomicAdd(&g_ccnt[row0+rlo], 1); if (s < MAXC) g_cand[(size_t)(row0+rlo)*MAXC + s] = col; }
            if (d01 < tlo){ int s = atomicAdd(&g_ccnt[row0+rlo], 1); if (s < MAXC) g_cand[(size_t)(row0+rlo)*MAXC + s] = col+1; }
            if (d10 < thi){ int s = atomicAdd(&g_ccnt[row0+rhi], 1); if (s < MAXC) g_cand[(size_t)(row0+rhi)*MAXC + s] = col; }
            if (d11 < thi){ int s = atomicAdd(&g_ccnt[row0+rhi], 1); if (s < MAXC) g_cand[(size_t)(row0+rhi)*MAXC + s] = col+1; }
        }
    }
}

// ---------------- phase 2: exact rescore of candidates ----------------
__global__ void rescore_kernel(const float* __restrict__ emb){
    __shared__ float srest[256];
    int row = blockIdx.x;
    int tid = threadIdx.x;
    srest[tid]       = g_rest[(size_t)row*Cc + tid];
    srest[tid + 128] = g_rest[(size_t)row*Cc + tid + 128];
    __syncthreads();
    int cnt = g_ccnt[row];
    if (cnt > MAXC) cnt = MAXC;
    float rsq = g_rsq[row];
    for (int t = tid; t < cnt; t += 128){
        int k = g_cand[(size_t)row*MAXC + t];
        const float* e = emb + (size_t)k*Cc;
        float acc = 0.0f;
        #pragma unroll 8
        for (int c=0;c<Cc;c++) acc = fmaf(srest[c], __ldg(e + c), acc);
        float d = fmaf(-2.0f, acc, rsq + g_esq[k]);
        unsigned long long key = ((unsigned long long)fkey(d) << 32) | (unsigned int)k;
        atomicMin(&g_win[row], key);
    }
}

// ---------------- winner gather / residual update / loss ----------------
__global__ void update_kernel(const float* __restrict__ f, const float* __restrict__ emb, int pn){
    __shared__ double sred[256];
    int bn = blockIdx.x;
    int b = bn >> 4, n = bn & 15;
    int c = threadIdx.x;

    float h;
    if (pn == Nn){
        int k0 = (int)(g_win[(size_t)b*pn + n] & 0xFFFFFFFFull);
        h = emb[(size_t)k0*Cc + c];
    } else {
        double scale = (double)pn / 16.0;
        double pos = ((double)n + 0.5)*scale - 0.5;
        if (pos < 0.0) pos = 0.0;
        int i0 = (int)floor(pos);
        if (i0 > pn-1) i0 = pn-1;
        double frac = pos - (double)i0;
        int i1 = i0 + 1; if (i1 > pn-1) i1 = pn-1;
        float w0 = (float)(1.0 - frac);
        int k0 = (int)(g_win[(size_t)b*pn + i0] & 0xFFFFFFFFull);
        if (i1 == i0){
            float w = (float)((double)w0 + frac);
            h = w * emb[(size_t)k0*Cc + c];
        } else {
            float w1 = (float)frac;
            int k1 = (int)(g_win[(size_t)b*pn + i1] & 0xFFFFFFFFull);
            h = fmaf(w1, emb[(size_t)k1*Cc + c], w0 * emb[(size_t)k0*Cc + c]);
        }
    }

    size_t idx = (size_t)bn*Cc + c;
    float fh = g_fhat[idx] + h;
    g_fhat[idx] = fh;
    g_frest[idx] = g_frest[idx] - h;
    float t = fh - f[idx];
    sred[c] = (double)t * (double)t;
    __syncthreads();
    for (int s=128;s>0;s>>=1){
        if (c < s) sred[c] += sred[c+s];
        __syncthreads();
    }
    if (c == 0) atomicAdd(&g_loss, sred[0]);
}

__global__ void finalize_kernel(float* __restrict__ out){
    int i = blockIdx.x*blockDim.x + threadIdx.x;
    if (i < Bb*Nn*Cc) out[i] = g_fhat[i];
    if (i == 0){
        double S = g_loss / (double)(Bb*Nn*Cc);
        out[Bb*Nn*Cc]     = (float)(0.25 * S / 16.0);   // commit
        out[Bb*Nn*Cc + 1] = (float)(S / 16.0);          // qlat
    }
}

extern "C" void kernel_launch(void* const* d_in, const int* in_sizes, int n_in,
                              void* d_out, int out_size){
    const float* f   = (const float*)d_in[0];
    const float* emb = (const float*)d_in[1];
    float* out = (float*)d_out;

    cudaFuncSetAttribute(gemm_filter_kernel, cudaFuncAttributeMaxDynamicSharedMemorySize, SMEM_GEMM);

    init_kernel<<<(Bb*Nn*Cc + 255)/256, 256>>>(f);
    prep_emb_kernel<<<(Kk + 255)/256, 256>>>(emb);

    for (int pn=1; pn<=Nn; pn++){
        int M = Bb*pn;
        pool_rsq_kernel<<<M, 256>>>(pn);
        dim3 grid(Kk/128, M/128);
        gemm_filter_kernel<<<grid, 512, SMEM_GEMM>>>();
        rescore_kernel<<<M, 128>>>(emb);
        update_kernel<<<Bb*Nn, 256>>>(f, emb, pn);
    }
    finalize_kernel<<<(Bb*Nn*Cc + 255)/256, 256>>>(out);
}